// round 5
// baseline (speedup 1.0000x reference)
#include <cuda_runtime.h>

#define CH 256
#define QEPS 1e-4f
#define NBLOCKS 444   // 3 per SM * 148, shared by reduce & apply (chunk-matched)

// Scratch (no allocations allowed).
__device__ float g_sums[14 * CH];
__device__ float g_M[16 * CH];
__device__ float g_bias[4 * CH];   // beta - M @ mu  (folded bias)

// ---------------------------------------------------------------------------
// Kernel 0: zero the reduction scratch (graph replays must be deterministic).
// ---------------------------------------------------------------------------
__global__ void k_zero() {
    int i = blockIdx.x * blockDim.x + threadIdx.x;
    if (i < 14 * CH) g_sums[i] = 0.0f;
}

// ---------------------------------------------------------------------------
// Kernel 1: per-channel sums/product-sums. Chunked blocks, ASCENDING order,
// default cache policy (lines stay L2-resident for k_apply's reverse pass).
// 2 rows per iteration (8 outstanding LDG.64), float2 lanes.
// ---------------------------------------------------------------------------
__global__ void __launch_bounds__(256, 3) k_reduce(const float* __restrict__ x,
                                                   int S, int rowsPerBlock) {
    const int t = threadIdx.x;
    const int g = t & 127;
    const int rq = t >> 7;

    const int s0 = blockIdx.x * rowsPerBlock;
    int send = s0 + rowsPerBlock;
    if (send > S) send = S;
    if (s0 >= S) return;

    const unsigned CS = (unsigned)S * CH;
    const unsigned gg = (unsigned)g * 2u;

    float2 a[14];
#pragma unroll
    for (int i = 0; i < 14; ++i) a[i] = make_float2(0.f, 0.f);

    const int nfull = (send - s0) >> 2;   // iterations covering 4 rows each

    for (int it = 0; it < nfull; ++it) {
        int s = s0 + 4 * it + rq;
        unsigned bA = (unsigned)s * CH + gg;
        unsigned bB = bA + 2u * CH;
        float2 xA0 = __ldg((const float2*)(x + bA));
        float2 xB0 = __ldg((const float2*)(x + bB));
        float2 xA1 = __ldg((const float2*)(x + CS + bA));
        float2 xB1 = __ldg((const float2*)(x + CS + bB));
        float2 xA2 = __ldg((const float2*)(x + 2 * CS + bA));
        float2 xB2 = __ldg((const float2*)(x + 2 * CS + bB));
        float2 xA3 = __ldg((const float2*)(x + 3 * CS + bA));
        float2 xB3 = __ldg((const float2*)(x + 3 * CS + bB));

        a[0].x += xA0.x + xB0.x;                a[0].y += xA0.y + xB0.y;
        a[1].x += xA1.x + xB1.x;                a[1].y += xA1.y + xB1.y;
        a[2].x += xA2.x + xB2.x;                a[2].y += xA2.y + xB2.y;
        a[3].x += xA3.x + xB3.x;                a[3].y += xA3.y + xB3.y;
        a[4].x += xA0.x * xA0.x + xB0.x * xB0.x; a[4].y += xA0.y * xA0.y + xB0.y * xB0.y;
        a[5].x += xA0.x * xA1.x + xB0.x * xB1.x; a[5].y += xA0.y * xA1.y + xB0.y * xB1.y;
        a[6].x += xA0.x * xA2.x + xB0.x * xB2.x; a[6].y += xA0.y * xA2.y + xB0.y * xB2.y;
        a[7].x += xA0.x * xA3.x + xB0.x * xB3.x; a[7].y += xA0.y * xA3.y + xB0.y * xB3.y;
        a[8].x += xA1.x * xA1.x + xB1.x * xB1.x; a[8].y += xA1.y * xA1.y + xB1.y * xB1.y;
        a[9].x += xA1.x * xA2.x + xB1.x * xB2.x; a[9].y += xA1.y * xA2.y + xB1.y * xB2.y;
        a[10].x += xA1.x * xA3.x + xB1.x * xB3.x; a[10].y += xA1.y * xA3.y + xB1.y * xB3.y;
        a[11].x += xA2.x * xA2.x + xB2.x * xB2.x; a[11].y += xA2.y * xA2.y + xB2.y * xB2.y;
        a[12].x += xA2.x * xA3.x + xB2.x * xB3.x; a[12].y += xA2.y * xA3.y + xB2.y * xB3.y;
        a[13].x += xA3.x * xA3.x + xB3.x * xB3.x; a[13].y += xA3.y * xA3.y + xB3.y * xB3.y;
    }
    // tail rows
    for (int s = s0 + 4 * nfull + rq; s < send; s += 2) {
        unsigned base = (unsigned)s * CH + gg;
        float2 x0 = __ldg((const float2*)(x + base));
        float2 x1 = __ldg((const float2*)(x + CS + base));
        float2 x2 = __ldg((const float2*)(x + 2 * CS + base));
        float2 x3 = __ldg((const float2*)(x + 3 * CS + base));
        a[0].x += x0.x; a[0].y += x0.y;
        a[1].x += x1.x; a[1].y += x1.y;
        a[2].x += x2.x; a[2].y += x2.y;
        a[3].x += x3.x; a[3].y += x3.y;
        a[4].x += x0.x * x0.x; a[4].y += x0.y * x0.y;
        a[5].x += x0.x * x1.x; a[5].y += x0.y * x1.y;
        a[6].x += x0.x * x2.x; a[6].y += x0.y * x2.y;
        a[7].x += x0.x * x3.x; a[7].y += x0.y * x3.y;
        a[8].x += x1.x * x1.x; a[8].y += x1.y * x1.y;
        a[9].x += x1.x * x2.x; a[9].y += x1.y * x2.y;
        a[10].x += x1.x * x3.x; a[10].y += x1.y * x3.y;
        a[11].x += x2.x * x2.x; a[11].y += x2.y * x2.y;
        a[12].x += x2.x * x3.x; a[12].y += x2.y * x3.y;
        a[13].x += x3.x * x3.x; a[13].y += x3.y * x3.y;
    }

    __shared__ float2 red[512];
#pragma unroll
    for (int i = 0; i < 14; i += 2) {
        red[t] = a[i];
        red[256 + t] = a[i + 1];
        __syncthreads();
        if (t < 128) {
            float2 v = red[t], w = red[t + 128];
            v.x += w.x; v.y += w.y;
            float* dst = &g_sums[i * CH + t * 2];
            atomicAdd(dst + 0, v.x);
            atomicAdd(dst + 1, v.y);
            v = red[256 + t]; w = red[256 + t + 128];
            v.x += w.x; v.y += w.y;
            dst = &g_sums[(i + 1) * CH + t * 2];
            atomicAdd(dst + 0, v.x);
            atomicAdd(dst + 1, v.y);
        }
        __syncthreads();
    }
}

// ---------------------------------------------------------------------------
// Kernel 2: stats -> whitening -> M = G @ W, and folded bias = beta - M @ mu.
// One block, thread = channel. Mirrors _whitening_matrix exactly.
// ---------------------------------------------------------------------------
__global__ void k_stats(const float* __restrict__ gamma,
                        const float* __restrict__ beta, int S) {
    const int c = threadIdx.x;
    const float invN = 1.0f / (float)S;

    float mu[4];
#pragma unroll
    for (int p = 0; p < 4; ++p) mu[p] = g_sums[p * CH + c] * invN;

    // cov entries: 0 rr,1 ri,2 rj,3 rk,4 ii,5 ij,6 ik,7 jj,8 jk,9 kk
    const int ta[10] = {0, 0, 0, 0, 1, 1, 1, 2, 2, 3};
    const int tb[10] = {0, 1, 2, 3, 1, 2, 3, 2, 3, 3};
    float v[10];
#pragma unroll
    for (int i = 0; i < 10; ++i) {
        v[i] = g_sums[(4 + i) * CH + c] * invN - mu[ta[i]] * mu[tb[i]];
        if (ta[i] == tb[i]) v[i] += QEPS;
    }

    float wrr = sqrtf(v[0]);
    float wri = v[1] / wrr;
    float wii = sqrtf(v[4] - wri * wri);
    float wrj = v[2] / wrr;
    float wij = (v[5] - wri * wrj) / wii;
    float wjj = sqrtf(v[7] - (wij * wij + wrj * wrj));
    float wrk = v[3] / wrr;
    float wik = (v[6] - wri * wrk) / wii;
    float wjk = (v[8] - (wij * wik + wrj * wrk)) / wjj;
    float wkk = sqrtf(v[9] - (wjk * wjk + wik * wik + wrk * wrk));

    float orr = 1.0f / wrr, oii = 1.0f / wii, ojj = 1.0f / wjj, okk = 1.0f / wkk;
    float ori = -(wri * orr) / wii;
    float orj = -(wrj * orr + wij * ori) / wjj;
    float ork = -(wrk * orr + wik * ori + wjk * orj) / wkk;
    float oij = -(wij * oii) / wjj;
    float oik = -(wik * oii + wjk * oij) / wkk;
    float ojk = -(wjk * ojj) / wkk;

    float W[4][4] = {{orr, ori, orj, ork},
                     {ori, oii, oij, oik},
                     {orj, oij, ojj, ojk},
                     {ork, oik, ojk, okk}};

    float g0 = gamma[0 * CH + c], g1 = gamma[1 * CH + c], g2 = gamma[2 * CH + c];
    float g3 = gamma[3 * CH + c], g4 = gamma[4 * CH + c], g5 = gamma[5 * CH + c];
    float g6 = gamma[6 * CH + c], g7 = gamma[7 * CH + c], g8 = gamma[8 * CH + c];
    float g9 = gamma[9 * CH + c];
    float G[4][4] = {{g0, g1, g2, g3},
                     {g1, g4, g5, g6},
                     {g2, g5, g7, g8},
                     {g3, g6, g8, g9}};

#pragma unroll
    for (int p = 0; p < 4; ++p) {
        float bias = beta[p * CH + c];
#pragma unroll
        for (int s = 0; s < 4; ++s) {
            float acc = 0.f;
#pragma unroll
            for (int q = 0; q < 4; ++q) acc += G[p][q] * W[q][s];
            g_M[(p * 4 + s) * CH + c] = acc;
            bias -= acc * mu[s];   // fold mean: bias' = beta - M @ mu
        }
        g_bias[p * CH + c] = bias;
    }
}

// ---------------------------------------------------------------------------
// Kernel 3: out[p] = sum_q M[p][q] * x[q] + bias'[p].
// SAME chunk partition as k_reduce, traversed in REVERSE so the tail of each
// chunk (still L2-resident from k_reduce) is read first. M + bias register-
// resident; 2 rows per iteration; streaming hints on x/out.
// ---------------------------------------------------------------------------
__global__ void __launch_bounds__(256, 3) k_apply(const float* __restrict__ x,
                                                  float* __restrict__ out,
                                                  int S, int rowsPerBlock) {
    const int t = threadIdx.x;
    const int g = t & 127;   // channel pair index
    const int rq = t >> 7;   // row phase (0..1)

    const float2* M2 = (const float2*)g_M;
    const float2* B2 = (const float2*)g_bias;

    float2 m[16], b[4];
#pragma unroll
    for (int i = 0; i < 16; ++i) m[i] = M2[i * 128 + g];
#pragma unroll
    for (int p = 0; p < 4; ++p) b[p] = B2[p * 128 + g];

    const int s0 = blockIdx.x * rowsPerBlock;
    int send = s0 + rowsPerBlock;
    if (send > S) send = S;
    if (s0 >= S) return;

    const unsigned CS = (unsigned)S * CH;
    const unsigned gg = (unsigned)g * 2u;
    const int nfull = (send - s0) >> 2;

    // tail first (highest rows = most recently cached by k_reduce)
    for (int s = s0 + 4 * nfull + rq; s < send; s += 2) {
        unsigned base = (unsigned)s * CH + gg;
        float2 x0 = __ldcs((const float2*)(x + base));
        float2 x1 = __ldcs((const float2*)(x + CS + base));
        float2 x2 = __ldcs((const float2*)(x + 2 * CS + base));
        float2 x3 = __ldcs((const float2*)(x + 3 * CS + base));
#pragma unroll
        for (int p = 0; p < 4; ++p) {
            float2 o = b[p];
            o.x += m[p * 4 + 0].x * x0.x; o.y += m[p * 4 + 0].y * x0.y;
            o.x += m[p * 4 + 1].x * x1.x; o.y += m[p * 4 + 1].y * x1.y;
            o.x += m[p * 4 + 2].x * x2.x; o.y += m[p * 4 + 2].y * x2.y;
            o.x += m[p * 4 + 3].x * x3.x; o.y += m[p * 4 + 3].y * x3.y;
            __stcs((float2*)(out + p * CS + base), o);
        }
    }

    // full iterations, descending through the chunk
    for (int it = nfull - 1; it >= 0; --it) {
        int s = s0 + 4 * it + rq;
        unsigned bA = (unsigned)s * CH + gg;
        unsigned bB = bA + 2u * CH;
        float2 xA0 = __ldcs((const float2*)(x + bA));
        float2 xB0 = __ldcs((const float2*)(x + bB));
        float2 xA1 = __ldcs((const float2*)(x + CS + bA));
        float2 xB1 = __ldcs((const float2*)(x + CS + bB));
        float2 xA2 = __ldcs((const float2*)(x + 2 * CS + bA));
        float2 xB2 = __ldcs((const float2*)(x + 2 * CS + bB));
        float2 xA3 = __ldcs((const float2*)(x + 3 * CS + bA));
        float2 xB3 = __ldcs((const float2*)(x + 3 * CS + bB));
#pragma unroll
        for (int p = 0; p < 4; ++p) {
            float2 oA = b[p], oB = b[p];
            oA.x += m[p * 4 + 0].x * xA0.x; oA.y += m[p * 4 + 0].y * xA0.y;
            oB.x += m[p * 4 + 0].x * xB0.x; oB.y += m[p * 4 + 0].y * xB0.y;
            oA.x += m[p * 4 + 1].x * xA1.x; oA.y += m[p * 4 + 1].y * xA1.y;
            oB.x += m[p * 4 + 1].x * xB1.x; oB.y += m[p * 4 + 1].y * xB1.y;
            oA.x += m[p * 4 + 2].x * xA2.x; oA.y += m[p * 4 + 2].y * xA2.y;
            oB.x += m[p * 4 + 2].x * xB2.x; oB.y += m[p * 4 + 2].y * xB2.y;
            oA.x += m[p * 4 + 3].x * xA3.x; oA.y += m[p * 4 + 3].y * xA3.y;
            oB.x += m[p * 4 + 3].x * xB3.x; oB.y += m[p * 4 + 3].y * xB3.y;
            __stcs((float2*)(out + p * CS + bA), oA);
            __stcs((float2*)(out + p * CS + bB), oB);
        }
    }
}

// ---------------------------------------------------------------------------
extern "C" void kernel_launch(void* const* d_in, const int* in_sizes, int n_in,
                              void* d_out, int out_size) {
    const float* x = (const float*)d_in[0];
    const float* gamma = (const float*)d_in[1];
    const float* beta = (const float*)d_in[2];
    float* out = (float*)d_out;

    const int S = in_sizes[0] / (4 * CH);  // spatial rows per component (B*H*W)
    const int rowsPerBlock = (S + NBLOCKS - 1) / NBLOCKS;

    k_zero<<<14, 256>>>();
    k_reduce<<<NBLOCKS, 256>>>(x, S, rowsPerBlock);
    k_stats<<<1, CH>>>(gamma, beta, S);
    k_apply<<<NBLOCKS, 256>>>(x, out, S, rowsPerBlock);
}

// round 6
// speedup vs baseline: 1.0334x; 1.0334x over previous
#include <cuda_runtime.h>

#define CH 256
#define QEPS 1e-4f
#define RBLOCKS 444   // 3 per SM * 148
#define ABLOCKS 444

// Scratch (no allocations allowed). Zero-initialized at module load; k_stats
// re-zeroes g_sums after consuming it, so every graph replay sees zeros.
__device__ float g_sums[14 * CH];
__device__ float g_M[16 * CH];
__device__ float g_bias[4 * CH];   // beta - M @ mu  (folded bias)

// ---------------------------------------------------------------------------
// Kernel 1: per-channel sums and product-sums, float2 over channels.
// thread: channel pair g = t&127, row phase rq = t>>7 (2 rows per step).
// 14 float2 register accumulators; streaming loads; unroll 4 for MLP.
// smem block-reduce over the 2 row-phase threads, then atomics.
// ---------------------------------------------------------------------------
__global__ void __launch_bounds__(256, 3) k_reduce(const float* __restrict__ x,
                                                   int S, int rowsPerBlock) {
    const int t = threadIdx.x;
    const int g = t & 127;
    const int rq = t >> 7;

    int s0 = blockIdx.x * rowsPerBlock;
    int send = s0 + rowsPerBlock;
    if (send > S) send = S;

    const unsigned CS = (unsigned)S * CH;

    float2 a[14];
#pragma unroll
    for (int i = 0; i < 14; ++i) a[i] = make_float2(0.f, 0.f);

#pragma unroll 4
    for (int s = s0 + rq; s < send; s += 2) {
        unsigned base = (unsigned)s * CH + (unsigned)g * 2u;
        float2 x0 = __ldcs((const float2*)(x + base));
        float2 x1 = __ldcs((const float2*)(x + CS + base));
        float2 x2 = __ldcs((const float2*)(x + 2 * CS + base));
        float2 x3 = __ldcs((const float2*)(x + 3 * CS + base));

        a[0].x += x0.x;        a[0].y += x0.y;
        a[1].x += x1.x;        a[1].y += x1.y;
        a[2].x += x2.x;        a[2].y += x2.y;
        a[3].x += x3.x;        a[3].y += x3.y;
        a[4].x += x0.x * x0.x; a[4].y += x0.y * x0.y;   // rr
        a[5].x += x0.x * x1.x; a[5].y += x0.y * x1.y;   // ri
        a[6].x += x0.x * x2.x; a[6].y += x0.y * x2.y;   // rj
        a[7].x += x0.x * x3.x; a[7].y += x0.y * x3.y;   // rk
        a[8].x += x1.x * x1.x; a[8].y += x1.y * x1.y;   // ii
        a[9].x += x1.x * x2.x; a[9].y += x1.y * x2.y;   // ij
        a[10].x += x1.x * x3.x; a[10].y += x1.y * x3.y; // ik
        a[11].x += x2.x * x2.x; a[11].y += x2.y * x2.y; // jj
        a[12].x += x2.x * x3.x; a[12].y += x2.y * x3.y; // jk
        a[13].x += x3.x * x3.x; a[13].y += x3.y * x3.y; // kk
    }

    __shared__ float2 red[512];
    // stage two accumulators per pass to halve the sync count
#pragma unroll
    for (int i = 0; i < 14; i += 2) {
        red[t] = a[i];
        red[256 + t] = a[i + 1];
        __syncthreads();
        if (t < 128) {
            float2 v = red[t], w = red[t + 128];
            v.x += w.x; v.y += w.y;
            float* dst = &g_sums[i * CH + t * 2];
            atomicAdd(dst + 0, v.x);
            atomicAdd(dst + 1, v.y);
            v = red[256 + t]; w = red[256 + t + 128];
            v.x += w.x; v.y += w.y;
            dst = &g_sums[(i + 1) * CH + t * 2];
            atomicAdd(dst + 0, v.x);
            atomicAdd(dst + 1, v.y);
        }
        __syncthreads();
    }
}

// ---------------------------------------------------------------------------
// Kernel 2: stats -> whitening -> M = G @ W, folded bias = beta - M @ mu.
// One block, thread = channel. Mirrors _whitening_matrix exactly.
// Afterwards zeroes g_sums so the next graph replay starts clean
// (replaces the separate k_zero kernel).
// ---------------------------------------------------------------------------
__global__ void k_stats(const float* __restrict__ gamma,
                        const float* __restrict__ beta, int S) {
    const int c = threadIdx.x;
    const float invN = 1.0f / (float)S;

    float mu[4];
#pragma unroll
    for (int p = 0; p < 4; ++p) mu[p] = g_sums[p * CH + c] * invN;

    // cov entries: 0 rr,1 ri,2 rj,3 rk,4 ii,5 ij,6 ik,7 jj,8 jk,9 kk
    const int ta[10] = {0, 0, 0, 0, 1, 1, 1, 2, 2, 3};
    const int tb[10] = {0, 1, 2, 3, 1, 2, 3, 2, 3, 3};
    float v[10];
#pragma unroll
    for (int i = 0; i < 10; ++i) {
        v[i] = g_sums[(4 + i) * CH + c] * invN - mu[ta[i]] * mu[tb[i]];
        if (ta[i] == tb[i]) v[i] += QEPS;
    }

    // consumed g_sums for this channel -> zero it for the next replay
#pragma unroll
    for (int i = 0; i < 14; ++i) g_sums[i * CH + c] = 0.0f;

    float wrr = sqrtf(v[0]);
    float wri = v[1] / wrr;
    float wii = sqrtf(v[4] - wri * wri);
    float wrj = v[2] / wrr;
    float wij = (v[5] - wri * wrj) / wii;
    float wjj = sqrtf(v[7] - (wij * wij + wrj * wrj));
    float wrk = v[3] / wrr;
    float wik = (v[6] - wri * wrk) / wii;
    float wjk = (v[8] - (wij * wik + wrj * wrk)) / wjj;
    float wkk = sqrtf(v[9] - (wjk * wjk + wik * wik + wrk * wrk));

    float orr = 1.0f / wrr, oii = 1.0f / wii, ojj = 1.0f / wjj, okk = 1.0f / wkk;
    float ori = -(wri * orr) / wii;
    float orj = -(wrj * orr + wij * ori) / wjj;
    float ork = -(wrk * orr + wik * ori + wjk * orj) / wkk;
    float oij = -(wij * oii) / wjj;
    float oik = -(wik * oii + wjk * oij) / wkk;
    float ojk = -(wjk * ojj) / wkk;

    float W[4][4] = {{orr, ori, orj, ork},
                     {ori, oii, oij, oik},
                     {orj, oij, ojj, ojk},
                     {ork, oik, ojk, okk}};

    float g0 = gamma[0 * CH + c], g1 = gamma[1 * CH + c], g2 = gamma[2 * CH + c];
    float g3 = gamma[3 * CH + c], g4 = gamma[4 * CH + c], g5 = gamma[5 * CH + c];
    float g6 = gamma[6 * CH + c], g7 = gamma[7 * CH + c], g8 = gamma[8 * CH + c];
    float g9 = gamma[9 * CH + c];
    float G[4][4] = {{g0, g1, g2, g3},
                     {g1, g4, g5, g6},
                     {g2, g5, g7, g8},
                     {g3, g6, g8, g9}};

#pragma unroll
    for (int p = 0; p < 4; ++p) {
        float bias = beta[p * CH + c];
#pragma unroll
        for (int s = 0; s < 4; ++s) {
            float acc = 0.f;
#pragma unroll
            for (int q = 0; q < 4; ++q) acc += G[p][q] * W[q][s];
            g_M[(p * 4 + s) * CH + c] = acc;
            bias -= acc * mu[s];   // fold mean: bias' = beta - M @ mu
        }
        g_bias[p * CH + c] = bias;
    }
}

// ---------------------------------------------------------------------------
// Kernel 3: out[p] = sum_q M[p][q] * x[q] + bias'[p].
// float2 over channels, M + bias register-resident, 2 spatial rows per
// iteration (8 outstanding LDG.64 per thread). Persistent grid-stride,
// streaming cache hints (zero reuse). launch_bounds(256,3) -> 24 warps/SM.
// ---------------------------------------------------------------------------
__global__ void __launch_bounds__(256, 3) k_apply(const float* __restrict__ x,
                                                  float* __restrict__ out, int S) {
    const int t = threadIdx.x;
    const int g = t & 127;   // channel pair index
    const int rq = t >> 7;   // row phase (0..1)

    const float2* M2 = (const float2*)g_M;
    const float2* B2 = (const float2*)g_bias;

    float2 m[16], b[4];
#pragma unroll
    for (int i = 0; i < 16; ++i) m[i] = M2[i * 128 + g];
#pragma unroll
    for (int p = 0; p < 4; ++p) b[p] = B2[p * 128 + g];

    const unsigned CS = (unsigned)S * CH;
    const unsigned stride = (unsigned)gridDim.x * 4u;   // 4 rows per block-iter
    const unsigned Sv = (unsigned)S & ~3u;              // multiple-of-4 body

    unsigned s = (unsigned)blockIdx.x * 4u + rq;
    for (; s + 2 < Sv; s += stride) {
        unsigned bA = s * CH + (unsigned)g * 2u;
        unsigned bB = bA + 2u * CH;                     // row s+2
        float2 xA0 = __ldcs((const float2*)(x + bA));
        float2 xB0 = __ldcs((const float2*)(x + bB));
        float2 xA1 = __ldcs((const float2*)(x + CS + bA));
        float2 xB1 = __ldcs((const float2*)(x + CS + bB));
        float2 xA2 = __ldcs((const float2*)(x + 2 * CS + bA));
        float2 xB2 = __ldcs((const float2*)(x + 2 * CS + bB));
        float2 xA3 = __ldcs((const float2*)(x + 3 * CS + bA));
        float2 xB3 = __ldcs((const float2*)(x + 3 * CS + bB));
#pragma unroll
        for (int p = 0; p < 4; ++p) {
            float2 oA = b[p], oB = b[p];
            oA.x += m[p * 4 + 0].x * xA0.x; oA.y += m[p * 4 + 0].y * xA0.y;
            oB.x += m[p * 4 + 0].x * xB0.x; oB.y += m[p * 4 + 0].y * xB0.y;
            oA.x += m[p * 4 + 1].x * xA1.x; oA.y += m[p * 4 + 1].y * xA1.y;
            oB.x += m[p * 4 + 1].x * xB1.x; oB.y += m[p * 4 + 1].y * xB1.y;
            oA.x += m[p * 4 + 2].x * xA2.x; oA.y += m[p * 4 + 2].y * xA2.y;
            oB.x += m[p * 4 + 2].x * xB2.x; oB.y += m[p * 4 + 2].y * xB2.y;
            oA.x += m[p * 4 + 3].x * xA3.x; oA.y += m[p * 4 + 3].y * xA3.y;
            oB.x += m[p * 4 + 3].x * xB3.x; oB.y += m[p * 4 + 3].y * xB3.y;
            __stcs((float2*)(out + p * CS + bA), oA);
            __stcs((float2*)(out + p * CS + bB), oB);
        }
    }
    // tail (also covers the residual rows when S % 4 != 0)
    for (; s < (unsigned)S; s += 2u) {
        unsigned base = s * CH + (unsigned)g * 2u;
        float2 x0 = __ldcs((const float2*)(x + base));
        float2 x1 = __ldcs((const float2*)(x + CS + base));
        float2 x2 = __ldcs((const float2*)(x + 2 * CS + base));
        float2 x3 = __ldcs((const float2*)(x + 3 * CS + base));
#pragma unroll
        for (int p = 0; p < 4; ++p) {
            float2 o = b[p];
            o.x += m[p * 4 + 0].x * x0.x; o.y += m[p * 4 + 0].y * x0.y;
            o.x += m[p * 4 + 1].x * x1.x; o.y += m[p * 4 + 1].y * x1.y;
            o.x += m[p * 4 + 2].x * x2.x; o.y += m[p * 4 + 2].y * x2.y;
            o.x += m[p * 4 + 3].x * x3.x; o.y += m[p * 4 + 3].y * x3.y;
            __stcs((float2*)(out + p * CS + base), o);
        }
    }
}

// ---------------------------------------------------------------------------
extern "C" void kernel_launch(void* const* d_in, const int* in_sizes, int n_in,
                              void* d_out, int out_size) {
    const float* x = (const float*)d_in[0];
    const float* gamma = (const float*)d_in[1];
    const float* beta = (const float*)d_in[2];
    float* out = (float*)d_out;

    const int S = in_sizes[0] / (4 * CH);  // spatial rows per component (B*H*W)
    const int rowsPerBlock = (S + RBLOCKS - 1) / RBLOCKS;

    k_reduce<<<RBLOCKS, 256>>>(x, S, rowsPerBlock);
    k_stats<<<1, CH>>>(gamma, beta, S);
    k_apply<<<ABLOCKS, 256>>>(x, out, S);
}